// round 6
// baseline (speedup 1.0000x reference)
#include <cuda_runtime.h>

// Patch2Im / fold (col2im) with averaging and crop.
// Input : x_patch [B=4, C=64, K=7, K=7, NH=85, NW=85] fp32 (row-major)
// Output: [B, C, 253, 253] fp32, where the padded full frame is 259x259
// (H = (85-1)*3 + 7) and we crop 3 on every side.
//
// Gather formulation: each thread owns 3 consecutive output columns
// ow = 3t+3 + e (e = 0,1,2). For kernel column j, the output with
// e = j%3 is the (only) one it touches, at patch column pw = t+1 - j/3.
// => per (i,j) plane, consecutive threads read consecutive addresses
//    (perfectly coalesced 128B warp transactions).
// Normalization count = (#valid i) * (#valid j), computed analytically.

namespace {
constexpr int K     = 7;
constexpr int NH    = 85;
constexpr int NW    = 85;
constexpr int PLANE = NH * NW;          // 7225
constexpr int PAD   = 3;
constexpr int HO    = 253;              // 259 - 3 - 3
constexpr int WO    = 253;
constexpr int BC    = 4 * 64;           // B*C grid dimension
constexpr int TPB   = 96;               // 85 compute lanes, padded to 3 warps
constexpr int TGRP  = 85;               // active column-group threads per row
}

__global__ __launch_bounds__(TPB)
void patch2im_kernel(const float* __restrict__ xp, float* __restrict__ out)
{
    const int h  = blockIdx.x;           // 0..252 output row
    const int bc = blockIdx.y;           // 0..255 fused batch*channel
    const int t  = threadIdx.x;          // 0..95

    __shared__ float sm[TGRP * 3];       // 255 staged output values

    const int oh = h + PAD;              // padded row coord, 3..255

    // Valid kernel-row offsets for this output row (same for whole block).
    // i in {oh%3, oh%3+3, oh%3+6} with ph=(oh-i)/3 in [0,NH)
    int offi[3];
    int ni = 0;
    const int ri = oh % 3;
    #pragma unroll
    for (int s = 0; s < 3; ++s) {
        const int i = ri + 3 * s;
        if (i < K) {
            const int d = oh - i;
            if (d >= 0) {
                const int ph = d / 3;    // exact (d % 3 == 0 by construction)
                if (ph < NH) offi[ni++] = i * K * PLANE + ph * NW;
            }
        }
    }

    if (t < TGRP) {
        const float* __restrict__ base = xp + (size_t)bc * (K * K * PLANE);

        float sum[3] = {0.f, 0.f, 0.f};
        int   njc[3] = {0, 0, 0};

        // For each kernel column j: e = j%3 selects which of this thread's
        // 3 outputs it feeds; pw = t + 1 - j/3 is the patch column.
        #pragma unroll
        for (int j = 0; j < K; ++j) {
            const int e  = j % 3;
            const int d  = j / 3;
            const int pw = t + 1 - d;
            if (pw >= 0 && pw < NW) {
                ++njc[e];
                const int offj = j * PLANE + pw;
                float acc = 0.f;
                #pragma unroll
                for (int a = 0; a < 3; ++a)
                    if (a < ni) acc += __ldg(base + offi[a] + offj);
                sum[e] += acc;
            }
        }

        // Normalize and stage into shared memory (stride-3 STS: bank-clean,
        // gcd(3,32)=1).
        #pragma unroll
        for (int e = 0; e < 3; ++e) {
            const int cnt = ni * njc[e];
            // cnt==0 only for the staged-but-never-read tail slots (w>=253)
            const float v = (cnt > 0) ? sum[e] / (float)cnt : 0.f;
            sm[3 * t + e] = v;
        }
    }

    __syncthreads();

    // Coalesced row store: 253 floats, 96 threads, 3 strided passes.
    float* __restrict__ orow = out + ((size_t)bc * HO + h) * WO;
    #pragma unroll
    for (int idx = 0; idx < 3; ++idx) {
        const int w = t + idx * TPB;
        if (w < WO) orow[w] = sm[w];
    }
}

extern "C" void kernel_launch(void* const* d_in, const int* in_sizes, int n_in,
                              void* d_out, int out_size)
{
    (void)in_sizes; (void)n_in; (void)out_size;
    const float* xp = (const float*)d_in[0];
    float* out = (float*)d_out;

    dim3 grid(HO, BC);   // 253 x 256 blocks
    dim3 block(TPB);
    patch2im_kernel<<<grid, block>>>(xp, out);
}

// round 7
// speedup vs baseline: 1.1958x; 1.1958x over previous
#include <cuda_runtime.h>

// Patch2Im / fold (col2im) with averaging and crop.
// Input : x_patch [B=4, C=64, K=7, K=7, NH=85, NW=85] fp32 (row-major)
// Output: [B, C, 253, 253] fp32 (padded frame 259x259, crop 3 each side)
//
// Gather formulation: thread t owns output columns ow = 3t+3+e (e=0,1,2).
// For kernel column j, the output with e=j%3 is touched at patch column
// pw = t+1 - j/3, i.e. all 7 loads of a kernel-row plane sit at FIXED
// immediate offsets from (plane_base + t):
//   j=0..6 -> {+1, P+1, 2P+1, 3P, 4P, 5P, 6P-1}   (P = 85*85)
// Consecutive threads read consecutive addresses -> perfect coalescing.
// Normalization counts are analytic; reciprocals are selected constants.

namespace {
constexpr int K     = 7;
constexpr int NH    = 85;
constexpr int NW    = 85;
constexpr int PLANE = NH * NW;          // 7225
constexpr int PAD   = 3;
constexpr int HO    = 253;
constexpr int WO    = 253;
constexpr int BC    = 4 * 64;
constexpr int TPB   = 96;               // 85 compute lanes + store helpers
constexpr int TGRP  = 85;
}

// Accumulate one kernel-row plane: 7 loads at constant immediate offsets,
// the two boundary groups predicated (compiles to @P LDG, no branches).
__device__ __forceinline__ void accum_plane(const float* __restrict__ q,
                                            bool p012, bool p6,
                                            float& a0, float& a1, float& a2)
{
    if (p012) {                               // pw = t+1 valid (t <= 83)
        a0 += __ldcs(q + 1);                  // j=0
        a1 += __ldcs(q + PLANE + 1);          // j=1
        a2 += __ldcs(q + 2 * PLANE + 1);      // j=2
    }
    a0 += __ldcs(q + 3 * PLANE);              // j=3 (pw = t, always valid)
    a1 += __ldcs(q + 4 * PLANE);              // j=4
    a2 += __ldcs(q + 5 * PLANE);              // j=5
    if (p6)                                   // pw = t-1 valid (t >= 1)
        a0 += __ldcs(q + 6 * PLANE - 1);      // j=6
}

__global__ __launch_bounds__(TPB)
void patch2im_kernel(const float* __restrict__ xp, float* __restrict__ out)
{
    const int h  = blockIdx.x;           // output row 0..252
    const int bc = blockIdx.y;           // fused batch*channel
    const int t  = threadIdx.x;          // 0..95

    __shared__ float sm[TGRP * 3];

    const int oh = h + PAD;              // padded row coord 3..255

    // Valid kernel-row plane offsets for this row (uniform per block).
    int offi[3];
    int ni = 0;
    const int ri = oh % 3;
    #pragma unroll
    for (int s = 0; s < 3; ++s) {
        const int i = ri + 3 * s;
        if (i < K) {
            const int d = oh - i;
            if (d >= 0) {
                const int ph = d / 3;
                if (ph < NH) offi[ni++] = i * (K * PLANE) + ph * NW;
            }
        }
    }
    // ni is always 2 or 3 for oh in [3, 255].

    if (t < TGRP) {
        const float* __restrict__ base =
            xp + (size_t)bc * (K * K * PLANE) + t;

        const bool p012 = (t <= NW - 2);   // t <= 83
        const bool p6   = (t >= 1);

        float a0 = 0.f, a1 = 0.f, a2 = 0.f;

        if (ni == 3) {                     // uniform branch (whole block)
            accum_plane(base + offi[0], p012, p6, a0, a1, a2);
            accum_plane(base + offi[1], p012, p6, a0, a1, a2);
            accum_plane(base + offi[2], p012, p6, a0, a1, a2);
            // counts: cnt0 = 3*nj0, cnt12 = 3*nj12
            const float inv0  = (p012 && p6) ? (1.f / 9.f) : (1.f / 6.f);
            const float inv12 = p012 ? (1.f / 6.f) : (1.f / 3.f);
            a0 *= inv0;  a1 *= inv12;  a2 *= inv12;
        } else {
            accum_plane(base + offi[0], p012, p6, a0, a1, a2);
            accum_plane(base + offi[1], p012, p6, a0, a1, a2);
            const float inv0  = (p012 && p6) ? (1.f / 6.f) : (1.f / 4.f);
            const float inv12 = p012 ? (1.f / 4.f) : (1.f / 2.f);
            a0 *= inv0;  a1 *= inv12;  a2 *= inv12;
        }

        // Stage: stride-3 STS, bank-conflict-free (gcd(3,32)=1).
        sm[3 * t + 0] = a0;
        sm[3 * t + 1] = a1;
        sm[3 * t + 2] = a2;
    }

    __syncthreads();

    // Coalesced row store: 253 floats with 96 threads, 3 passes.
    float* __restrict__ orow = out + ((size_t)bc * HO + h) * WO;
    #pragma unroll
    for (int idx = 0; idx < 3; ++idx) {
        const int w = t + idx * TPB;
        if (w < WO) orow[w] = sm[w];
    }
}

extern "C" void kernel_launch(void* const* d_in, const int* in_sizes, int n_in,
                              void* d_out, int out_size)
{
    (void)in_sizes; (void)n_in; (void)out_size;
    const float* xp = (const float*)d_in[0];
    float* out = (float*)d_out;

    dim3 grid(HO, BC);   // 253 x 256
    dim3 block(TPB);
    patch2im_kernel<<<grid, block>>>(xp, out);
}